// round 14
// baseline (speedup 1.0000x reference)
#include <cuda_runtime.h>
#include <cmath>

#define BB 128
#define LL 512
#define HH 512
#define TT 24
#define TAG_START 22
#define TAG_STOP  23
#define SEG 16
#define SS  32            // steps per segment = LL/SEG

// Scratch (device globals; no allocations).
__device__ float g_P[BB * SEG * 576];        // segment transport matrices 4.7 MB
__device__ int   g_M[BB * SEG];              // segment exponent offsets
__device__ int   g_cnt[BB];                  // last-CTA arrival counters (0-init)

// m16n8k8 tf32 mma (phase 2)
#define MMA_TF32(c0,c1,c2,c3,a0,a1,a2,a3,b0,b1) \
  asm("mma.sync.aligned.m16n8k8.row.col.f32.tf32.tf32.f32 " \
      "{%0,%1,%2,%3},{%4,%5,%6,%7},{%8,%9},{%0,%1,%2,%3};" \
      : "+f"(c0),"+f"(c1),"+f"(c2),"+f"(c3) \
      : "r"(a0),"r"(a1),"r"(a2),"r"(a3),"r"(b0),"r"(b1))

// m16n8k16 bf16 mma (phase 1)
#define MMA_BF16(c0,c1,c2,c3,a0,a1,a2,a3,b0,b1) \
  asm("mma.sync.aligned.m16n8k16.row.col.f32.bf16.bf16.f32 " \
      "{%0,%1,%2,%3},{%4,%5,%6,%7},{%8,%9},{%0,%1,%2,%3};" \
      : "+f"(c0),"+f"(c1),"+f"(c2),"+f"(c3) \
      : "r"(a0),"r"(a1),"r"(a2),"r"(a3),"r"(b0),"r"(b1))

__device__ __forceinline__ unsigned f2tf32(float v) {
    unsigned r;
    asm("cvt.rna.tf32.f32 %0, %1;" : "=r"(r) : "f"(v));
    return r;
}

__device__ __forceinline__ unsigned pk_bf16x2(float lo, float hi) {
    unsigned r;
    asm("cvt.rn.bf16x2.f32 %0, %1, %2;" : "=r"(r) : "f"(hi), "f"(lo));
    return r;
}

#define CP_ASYNC16(dst, src) \
    asm volatile("cp.async.cg.shared.global [%0], [%1], 16;" \
                 :: "r"(dst), "l"(src))
#define CP_COMMIT()  asm volatile("cp.async.commit_group;")
#define CP_WAIT(n)   asm volatile("cp.async.wait_group %0;" :: "n"(n))

#define SK 520    // Wtn row stride in bf16 units
#define SAF 36    // A-stage row stride in fp32 units (32 used + 4 pad)
#define CCOL 32
#define NCH 16

// ---------------------------------------------------------------------------
// Fully fused kernel: emission GEMM (bf16 mma, cp.async-streamed A) +
// per-segment transport chain (tf32 mma) + last-CTA-per-batch combine.
// One CTA = 4 warps = 4 segments = one batch's 128-row l-window.
// ---------------------------------------------------------------------------
__global__ void __launch_bounds__(128, 2) fused_kernel(
    const float* __restrict__ feat,
    const float* __restrict__ Wm,
    const float* __restrict__ bias,
    const float* __restrict__ trans,
    const int*   __restrict__ lengths,
    float*       __restrict__ out)
{
    __shared__ unsigned short Wtn[TT * SK];   // 24.4 KB bf16 W^T [n][k]
    __shared__ float As[4][128 * SAF];        // 73.7 KB A ring / Psm / P stage
    __shared__ float xsm[4][SS * TT];         // 12.3 KB emissions per warp
    __shared__ __align__(16) float wbuf[2][32];
    __shared__ int   isLast, mtot_sh;

    const int tid = threadIdx.x;
    const int b    = blockIdx.x >> 2;
    const int quad = blockIdx.x & 3;
    const long rowCTA = (long)b * LL + quad * 128;

    const int row16 = tid >> 3;
    const int col4  = tid & 7;

    // ---- phase 1 prologue: start chunks 0..2 streaming
    #pragma unroll
    for (int c = 0; c < 3; ++c) {
        #pragma unroll
        for (int i = 0; i < 8; ++i) {
            const int row = row16 + 16 * i;
            const float* src = feat + (rowCTA + row) * HH + c * CCOL + col4 * 4;
            const unsigned dst = (unsigned)__cvta_generic_to_shared(
                &As[c][row * SAF + col4 * 4]);
            CP_ASYNC16(dst, src);
        }
        CP_COMMIT();
    }

    for (int idx = tid; idx < TT * (HH / 4); idx += 128) {
        const int n  = idx >> 7;
        const int kq = idx & 127;
        const float4 wv = *reinterpret_cast<const float4*>(Wm + n * HH + kq * 4);
        uint2 p;
        p.x = pk_bf16x2(wv.x, wv.y);
        p.y = pk_bf16x2(wv.z, wv.w);
        *reinterpret_cast<uint2*>(&Wtn[n * SK + kq * 4]) = p;
    }

    const int lane = tid & 31;
    const int wid  = tid >> 5;
    const int g = lane >> 2;
    const int q = lane & 3;

    float C[2][3][4];
    #pragma unroll
    for (int mm = 0; mm < 2; ++mm)
        #pragma unroll
        for (int nt = 0; nt < 3; ++nt)
            { C[mm][nt][0]=0.f; C[mm][nt][1]=0.f; C[mm][nt][2]=0.f; C[mm][nt][3]=0.f; }

    // ---- phase 1 main loop
    #pragma unroll
    for (int c = 0; c < NCH; ++c) {
        CP_WAIT(2);
        __syncthreads();

        if (c + 3 < NCH) {
            const int cn = c + 3;
            #pragma unroll
            for (int i = 0; i < 8; ++i) {
                const int row = row16 + 16 * i;
                const float* src =
                    feat + (rowCTA + row) * HH + cn * CCOL + col4 * 4;
                const unsigned dst = (unsigned)__cvta_generic_to_shared(
                    &As[cn & 3][row * SAF + col4 * 4]);
                CP_ASYNC16(dst, src);
            }
        }
        CP_COMMIT();

        const float* Ac = &As[c & 3][0];
        #pragma unroll
        for (int kk = 0; kk < 2; ++kk) {
            const int kl = kk * 16;
            const int kg = c * CCOL + kl;
            #pragma unroll
            for (int mm = 0; mm < 2; ++mm) {
                const int r = wid * 32 + mm * 16 + g;
                const float2 f0 = *reinterpret_cast<const float2*>(
                    &Ac[r * SAF + kl + 2 * q]);
                const float2 f1 = *reinterpret_cast<const float2*>(
                    &Ac[(r + 8) * SAF + kl + 2 * q]);
                const float2 f2 = *reinterpret_cast<const float2*>(
                    &Ac[r * SAF + kl + 8 + 2 * q]);
                const float2 f3 = *reinterpret_cast<const float2*>(
                    &Ac[(r + 8) * SAF + kl + 8 + 2 * q]);
                const unsigned a0 = pk_bf16x2(f0.x, f0.y);
                const unsigned a1 = pk_bf16x2(f1.x, f1.y);
                const unsigned a2 = pk_bf16x2(f2.x, f2.y);
                const unsigned a3 = pk_bf16x2(f3.x, f3.y);
                #pragma unroll
                for (int nt = 0; nt < 3; ++nt) {
                    const int n = 8 * nt + g;
                    const unsigned b0 = *reinterpret_cast<const unsigned*>(
                        &Wtn[n * SK + kg + 2 * q]);
                    const unsigned b1 = *reinterpret_cast<const unsigned*>(
                        &Wtn[n * SK + kg + 8 + 2 * q]);
                    MMA_BF16(C[mm][nt][0], C[mm][nt][1], C[mm][nt][2], C[mm][nt][3],
                             a0, a1, a2, a3, b0, b1);
                }
            }
        }
    }
    CP_WAIT(0);

    // ---- epilogue: bias + exp -> xsm
    #pragma unroll
    for (int mm = 0; mm < 2; ++mm) {
        const int i0 = mm * 16 + g;
        #pragma unroll
        for (int nt = 0; nt < 3; ++nt) {
            const int col = nt * 8 + 2 * q;
            const float bv0 = __ldg(bias + col);
            const float bv1 = __ldg(bias + col + 1);
            *reinterpret_cast<float2*>(&xsm[wid][i0 * TT + col]) =
                make_float2(__expf(C[mm][nt][0] + bv0),
                            __expf(C[mm][nt][1] + bv1));
            *reinterpret_cast<float2*>(&xsm[wid][(i0 + 8) * TT + col]) =
                make_float2(__expf(C[mm][nt][2] + bv0),
                            __expf(C[mm][nt][3] + bv1));
        }
    }
    __syncthreads();

    // ================= phase 2: segment transport chain =================
    const int gseg = quad * 4 + wid;
    const int len = lengths[b];
    int steps = len - gseg * SS;
    steps = (steps < 0) ? 0 : ((steps > SS) ? SS : steps);

    unsigned A[2][3][4];
    #pragma unroll
    for (int m = 0; m < 2; ++m) {
        const int r0 = 16 * m + g;
        const int r1 = r0 + 8;
        #pragma unroll
        for (int ks = 0; ks < 3; ++ks) {
            const int c0 = 8 * ks + q;
            const int c1 = c0 + 4;
            A[m][ks][0] = (r0 < TT) ? f2tf32(__expf(trans[r0 * TT + c0])) : 0u;
            A[m][ks][1] = (r1 < TT) ? f2tf32(__expf(trans[r1 * TT + c0])) : 0u;
            A[m][ks][2] = (r0 < TT) ? f2tf32(__expf(trans[r0 * TT + c1])) : 0u;
            A[m][ks][3] = (r1 < TT) ? f2tf32(__expf(trans[r1 * TT + c1])) : 0u;
        }
    }

    #pragma unroll
    for (int m = 0; m < 2; ++m) {
        const int r0 = 16 * m + g;
        const int r1 = r0 + 8;
        #pragma unroll
        for (int nt = 0; nt < 3; ++nt) {
            const int col0 = 8 * nt + 2 * q;
            const int col1 = col0 + 1;
            C[m][nt][0] = (r0 == col0) ? 1.f : 0.f;
            C[m][nt][1] = (r0 == col1) ? 1.f : 0.f;
            C[m][nt][2] = (r1 == col0 && r1 < TT) ? 1.f : 0.f;
            C[m][nt][3] = (r1 == col1 && r1 < TT) ? 1.f : 0.f;
        }
    }

    float* Psm = reinterpret_cast<float*>(&As[0][0]) + wid * 2 * 672;
    int Mexp = 0;

    for (int i = 0; i < steps; ++i) {
        float* Ps = Psm + (i & 1) * 672;

        #pragma unroll
        for (int nt = 0; nt < 3; ++nt) {
            const int col = 8 * nt + 2 * q;
            *reinterpret_cast<float2*>(&Ps[g * 28 + col]) =
                make_float2(C[0][nt][0], C[0][nt][1]);
            *reinterpret_cast<float2*>(&Ps[(g + 8) * 28 + col]) =
                make_float2(C[0][nt][2], C[0][nt][3]);
            *reinterpret_cast<float2*>(&Ps[(16 + g) * 28 + col]) =
                make_float2(C[1][nt][0], C[1][nt][1]);
        }
        __syncwarp();

        unsigned Bf[3][3][2];
        #pragma unroll
        for (int ks = 0; ks < 3; ++ks)
            #pragma unroll
            for (int nt = 0; nt < 3; ++nt) {
                Bf[ks][nt][0] = f2tf32(Ps[(q + 8 * ks) * 28 + g + 8 * nt]);
                Bf[ks][nt][1] = f2tf32(Ps[(q + 4 + 8 * ks) * 28 + g + 8 * nt]);
            }

        const float x0 = xsm[wid][i * TT + g];
        const float x1 = xsm[wid][i * TT + g + 8];
        const float x2 = xsm[wid][i * TT + 16 + g];

        float Q[2][3][4];
        #pragma unroll
        for (int m = 0; m < 2; ++m)
            #pragma unroll
            for (int nt = 0; nt < 3; ++nt) {
                Q[m][nt][0] = 0.f; Q[m][nt][1] = 0.f;
                Q[m][nt][2] = 0.f; Q[m][nt][3] = 0.f;
                #pragma unroll
                for (int ks = 0; ks < 3; ++ks)
                    MMA_TF32(Q[m][nt][0], Q[m][nt][1], Q[m][nt][2], Q[m][nt][3],
                             A[m][ks][0], A[m][ks][1], A[m][ks][2], A[m][ks][3],
                             Bf[ks][nt][0], Bf[ks][nt][1]);
            }

        #pragma unroll
        for (int nt = 0; nt < 3; ++nt) {
            C[0][nt][0] = x0 * Q[0][nt][0];  C[0][nt][1] = x0 * Q[0][nt][1];
            C[0][nt][2] = x1 * Q[0][nt][2];  C[0][nt][3] = x1 * Q[0][nt][3];
            C[1][nt][0] = x2 * Q[1][nt][0];  C[1][nt][1] = x2 * Q[1][nt][1];
            C[1][nt][2] = 0.f;               C[1][nt][3] = 0.f;
        }

        if ((i & 3) == 3) {
            float mx = 0.f;
            #pragma unroll
            for (int m = 0; m < 2; ++m)
                #pragma unroll
                for (int nt = 0; nt < 3; ++nt) {
                    mx = fmaxf(mx, fmaxf(C[m][nt][0], C[m][nt][1]));
                    mx = fmaxf(mx, fmaxf(C[m][nt][2], C[m][nt][3]));
                }
            const unsigned mb =
                __reduce_max_sync(0xffffffffu, __float_as_uint(mx));
            const int e  = (int)(mb >> 23);
            const int en = (e == 0) ? 127 : e;
            const float nsc = __uint_as_float((unsigned)(254 - en) << 23);
            #pragma unroll
            for (int m = 0; m < 2; ++m)
                #pragma unroll
                for (int nt = 0; nt < 3; ++nt) {
                    C[m][nt][0] *= nsc; C[m][nt][1] *= nsc;
                    C[m][nt][2] *= nsc; C[m][nt][3] *= nsc;
                }
            Mexp += (en - 127);
        }
    }

    // store P_g and Mexp
    const int idx = b * SEG + gseg;
    float* Pg = g_P + (size_t)idx * 576;
    #pragma unroll
    for (int nt = 0; nt < 3; ++nt) {
        const int col = 8 * nt + 2 * q;
        *reinterpret_cast<float2*>(&Pg[g * TT + col]) =
            make_float2(C[0][nt][0], C[0][nt][1]);
        *reinterpret_cast<float2*>(&Pg[(g + 8) * TT + col]) =
            make_float2(C[0][nt][2], C[0][nt][3]);
        *reinterpret_cast<float2*>(&Pg[(16 + g) * TT + col]) =
            make_float2(C[1][nt][0], C[1][nt][1]);
    }
    if (lane == 0) g_M[idx] = Mexp;

    // ============== last-CTA-per-batch combine (release/acquire) =========
    __threadfence();          // release our P/M stores (all threads)
    __syncthreads();
    if (tid == 0)
        isLast = (atomicAdd(&g_cnt[b], 1) == 3);
    __syncthreads();
    if (!isLast) return;
    __threadfence();          // acquire peers' P/M stores

    // stage all 16 P matrices into the dead As ring (coalesced, 128 threads)
    float* Pall = reinterpret_cast<float*>(&As[0][0]);
    const float* gsrc = g_P + (size_t)b * SEG * 576;
    for (int i = tid; i < SEG * 576 / 4; i += 128)
        *reinterpret_cast<float4*>(Pall + i * 4) =
            *reinterpret_cast<const float4*>(gsrc + i * 4);

    if (tid == 0) {
        int s = 0;
        #pragma unroll
        for (int g2 = 0; g2 < SEG; ++g2) s += g_M[b * SEG + g2];
        mtot_sh = s;
        g_cnt[b] = 0;        // reset for next graph replay
    }
    __syncthreads();

    if (wid == 0) {
        const int lanec = (lane < TT) ? lane : (TT - 1);
        const float u = (lane < TT) ? __expf(trans[TAG_STOP * TT + lane]) : 0.f;
        float v = (lane == TAG_START) ? 1.f : 0.f;
        int Mtot = mtot_sh;

        #pragma unroll
        for (int g2 = 0; g2 < SEG; ++g2) {
            const int p = g2 & 1;
            wbuf[p][lane] = v;
            __syncwarp();

            const float* Pr = Pall + g2 * 576 + lanec * TT;
            const float4* vv = reinterpret_cast<const float4*>(&wbuf[p][0]);
            float a0 = 0.f, a1 = 0.f, a2 = 0.f, a3 = 0.f;
            #pragma unroll
            for (int i = 0; i < 6; ++i) {
                const float4 rr = *reinterpret_cast<const float4*>(Pr + i * 4);
                const float4 w4 = vv[i];
                a0 = fmaf(rr.x, w4.x, a0);
                a1 = fmaf(rr.y, w4.y, a1);
                a2 = fmaf(rr.z, w4.z, a2);
                a3 = fmaf(rr.w, w4.w, a3);
            }
            float vn = (a0 + a1) + (a2 + a3);
            vn = (lane < TT) ? vn : 0.f;

            const unsigned mb =
                __reduce_max_sync(0xffffffffu, __float_as_uint(vn));
            const int e  = (int)(mb >> 23);
            const int en = (e == 0) ? 127 : e;
            const float nsc = __uint_as_float((unsigned)(254 - en) << 23);
            v = vn * nsc;
            Mtot += (en - 127);
        }

        float term = v * u;
        #pragma unroll
        for (int o = 16; o > 0; o >>= 1)
            term += __shfl_xor_sync(0xffffffffu, term, o);

        if (lane == 0)
            out[b] = __logf(term) + (float)Mtot * 0.69314718055994531f;
    }
}

extern "C" void kernel_launch(void* const* d_in, const int* in_sizes, int n_in,
                              void* d_out, int out_size)
{
    const float* feat   = (const float*)d_in[0];  // [128,512,512]
    const float* Wm     = (const float*)d_in[1];  // [24,512]
    const float* bias   = (const float*)d_in[2];  // [24]
    const float* trans  = (const float*)d_in[3];  // [24,24]
    const int*   lens   = (const int*)d_in[4];    // [128]
    float* out = (float*)d_out;                   // [128]

    fused_kernel<<<512, 128>>>(feat, Wm, bias, trans, lens, out);
}

// round 15
// speedup vs baseline: 1.0314x; 1.0314x over previous
#include <cuda_runtime.h>
#include <cmath>

#define BB 128
#define LL 512
#define HH 512
#define TT 24
#define TAG_START 22
#define TAG_STOP  23
#define SEG 16
#define SS  32            // steps per segment = LL/SEG

// Scratch (device globals; no allocations).
__device__ float g_P[BB * SEG * 576];        // segment transport matrices 4.7 MB
__device__ int   g_M[BB * SEG];              // segment exponent offsets

// m16n8k8 tf32 mma (phase 2)
#define MMA_TF32(c0,c1,c2,c3,a0,a1,a2,a3,b0,b1) \
  asm("mma.sync.aligned.m16n8k8.row.col.f32.tf32.tf32.f32 " \
      "{%0,%1,%2,%3},{%4,%5,%6,%7},{%8,%9},{%0,%1,%2,%3};" \
      : "+f"(c0),"+f"(c1),"+f"(c2),"+f"(c3) \
      : "r"(a0),"r"(a1),"r"(a2),"r"(a3),"r"(b0),"r"(b1))

// m16n8k16 bf16 mma (phase 1)
#define MMA_BF16(c0,c1,c2,c3,a0,a1,a2,a3,b0,b1) \
  asm("mma.sync.aligned.m16n8k16.row.col.f32.bf16.bf16.f32 " \
      "{%0,%1,%2,%3},{%4,%5,%6,%7},{%8,%9},{%0,%1,%2,%3};" \
      : "+f"(c0),"+f"(c1),"+f"(c2),"+f"(c3) \
      : "r"(a0),"r"(a1),"r"(a2),"r"(a3),"r"(b0),"r"(b1))

__device__ __forceinline__ unsigned f2tf32(float v) {
    unsigned r;
    asm("cvt.rna.tf32.f32 %0, %1;" : "=r"(r) : "f"(v));
    return r;
}

__device__ __forceinline__ unsigned pk_bf16x2(float lo, float hi) {
    unsigned r;
    asm("cvt.rn.bf16x2.f32 %0, %1, %2;" : "=r"(r) : "f"(hi), "f"(lo));
    return r;
}

#define CP_ASYNC16(dst, src) \
    asm volatile("cp.async.cg.shared.global [%0], [%1], 16;" \
                 :: "r"(dst), "l"(src))
#define CP_COMMIT()  asm volatile("cp.async.commit_group;")
#define CP_WAIT(n)   asm volatile("cp.async.wait_group %0;" :: "n"(n))

#define SK 520    // Wtn row stride in bf16 units
#define SAF 20    // A-stage row stride in fp32 units (16 used + 4 pad)
#define CCOL 16   // columns per chunk
#define NCH 32    // chunks (= HH / CCOL)

// ---------------------------------------------------------------------------
// Fused kernel: emission GEMM (bf16 mma, cp.async 16-col chunks) + per-segment
// transport chain (tf32 mma).  smem ~72KB -> 3 CTAs/SM (was 110KB -> 2).
// One CTA = 4 warps = 4 segments = one batch's 128-row l-window.
// ---------------------------------------------------------------------------
__global__ void __launch_bounds__(128, 3) fused_kernel(
    const float* __restrict__ feat,
    const float* __restrict__ Wm,
    const float* __restrict__ bias,
    const float* __restrict__ trans,
    const int*   __restrict__ lengths)
{
    __shared__ unsigned short Wtn[TT * SK];       // 24.4 KB bf16 W^T [n][k]
    __shared__ float As[4][128 * SAF];            // 40.96 KB A ring / Psm
    __shared__ unsigned short xsm[4][SS * TT];    // 6.1 KB emissions (bf16)

    const int tid = threadIdx.x;
    const int b    = blockIdx.x >> 2;
    const int quad = blockIdx.x & 3;
    const long rowCTA = (long)b * LL + quad * 128;

    // cp.async mapping: 128 rows x 16 cols fp32 = 512 x 16B; 4 per thread
    const int rowa = tid >> 2;     // 0..31
    const int col4 = tid & 3;      // float4 index within 16-col chunk

    // ---- phase 1 prologue: start chunks 0..2 streaming
    #pragma unroll
    for (int c = 0; c < 3; ++c) {
        #pragma unroll
        for (int i = 0; i < 4; ++i) {
            const int row = rowa + 32 * i;
            const float* src = feat + (rowCTA + row) * HH + c * CCOL + col4 * 4;
            const unsigned dst = (unsigned)__cvta_generic_to_shared(
                &As[c][row * SAF + col4 * 4]);
            CP_ASYNC16(dst, src);
        }
        CP_COMMIT();
    }

    // stage Wtn under the async loads
    for (int idx = tid; idx < TT * (HH / 4); idx += 128) {
        const int n  = idx >> 7;
        const int kq = idx & 127;
        const float4 wv = *reinterpret_cast<const float4*>(Wm + n * HH + kq * 4);
        uint2 p;
        p.x = pk_bf16x2(wv.x, wv.y);
        p.y = pk_bf16x2(wv.z, wv.w);
        *reinterpret_cast<uint2*>(&Wtn[n * SK + kq * 4]) = p;
    }

    const int lane = tid & 31;
    const int wid  = tid >> 5;
    const int g = lane >> 2;
    const int q = lane & 3;

    float C[2][3][4];
    #pragma unroll
    for (int mm = 0; mm < 2; ++mm)
        #pragma unroll
        for (int nt = 0; nt < 3; ++nt)
            { C[mm][nt][0]=0.f; C[mm][nt][1]=0.f; C[mm][nt][2]=0.f; C[mm][nt][3]=0.f; }

    // ---- phase 1 main loop: 32 chunks of 16 columns (one k16 step each)
    #pragma unroll 4
    for (int c = 0; c < NCH; ++c) {
        CP_WAIT(2);
        __syncthreads();

        if (c + 3 < NCH) {
            const int cn = c + 3;
            #pragma unroll
            for (int i = 0; i < 4; ++i) {
                const int row = rowa + 32 * i;
                const float* src =
                    feat + (rowCTA + row) * HH + cn * CCOL + col4 * 4;
                const unsigned dst = (unsigned)__cvta_generic_to_shared(
                    &As[cn & 3][row * SAF + col4 * 4]);
                CP_ASYNC16(dst, src);
            }
        }
        CP_COMMIT();

        const float* Ac = &As[c & 3][0];
        const int kg = c * CCOL;
        #pragma unroll
        for (int mm = 0; mm < 2; ++mm) {
            const int r = wid * 32 + mm * 16 + g;
            const float2 f0 = *reinterpret_cast<const float2*>(
                &Ac[r * SAF + 2 * q]);
            const float2 f1 = *reinterpret_cast<const float2*>(
                &Ac[(r + 8) * SAF + 2 * q]);
            const float2 f2 = *reinterpret_cast<const float2*>(
                &Ac[r * SAF + 8 + 2 * q]);
            const float2 f3 = *reinterpret_cast<const float2*>(
                &Ac[(r + 8) * SAF + 8 + 2 * q]);
            const unsigned a0 = pk_bf16x2(f0.x, f0.y);
            const unsigned a1 = pk_bf16x2(f1.x, f1.y);
            const unsigned a2 = pk_bf16x2(f2.x, f2.y);
            const unsigned a3 = pk_bf16x2(f3.x, f3.y);
            #pragma unroll
            for (int nt = 0; nt < 3; ++nt) {
                const int n = 8 * nt + g;
                const unsigned b0 = *reinterpret_cast<const unsigned*>(
                    &Wtn[n * SK + kg + 2 * q]);
                const unsigned b1 = *reinterpret_cast<const unsigned*>(
                    &Wtn[n * SK + kg + 8 + 2 * q]);
                MMA_BF16(C[mm][nt][0], C[mm][nt][1], C[mm][nt][2], C[mm][nt][3],
                         a0, a1, a2, a3, b0, b1);
            }
        }
    }
    CP_WAIT(0);

    // ---- epilogue: bias + exp -> xsm (bf16)
    #pragma unroll
    for (int mm = 0; mm < 2; ++mm) {
        const int i0 = mm * 16 + g;
        #pragma unroll
        for (int nt = 0; nt < 3; ++nt) {
            const int col = nt * 8 + 2 * q;
            const float bv0 = __ldg(bias + col);
            const float bv1 = __ldg(bias + col + 1);
            *reinterpret_cast<unsigned*>(&xsm[wid][i0 * TT + col]) =
                pk_bf16x2(__expf(C[mm][nt][0] + bv0),
                          __expf(C[mm][nt][1] + bv1));
            *reinterpret_cast<unsigned*>(&xsm[wid][(i0 + 8) * TT + col]) =
                pk_bf16x2(__expf(C[mm][nt][2] + bv0),
                          __expf(C[mm][nt][3] + bv1));
        }
    }
    __syncthreads();   // ring dead, xsm complete -> phase 2 may reuse As

    // ================= phase 2: segment transport chain =================
    const int gseg = quad * 4 + wid;
    const int len = lengths[b];
    int steps = len - gseg * SS;
    steps = (steps < 0) ? 0 : ((steps > SS) ? SS : steps);

    unsigned A[2][3][4];
    #pragma unroll
    for (int m = 0; m < 2; ++m) {
        const int r0 = 16 * m + g;
        const int r1 = r0 + 8;
        #pragma unroll
        for (int ks = 0; ks < 3; ++ks) {
            const int c0 = 8 * ks + q;
            const int c1 = c0 + 4;
            A[m][ks][0] = (r0 < TT) ? f2tf32(__expf(trans[r0 * TT + c0])) : 0u;
            A[m][ks][1] = (r1 < TT) ? f2tf32(__expf(trans[r1 * TT + c0])) : 0u;
            A[m][ks][2] = (r0 < TT) ? f2tf32(__expf(trans[r0 * TT + c1])) : 0u;
            A[m][ks][3] = (r1 < TT) ? f2tf32(__expf(trans[r1 * TT + c1])) : 0u;
        }
    }

    #pragma unroll
    for (int m = 0; m < 2; ++m) {
        const int r0 = 16 * m + g;
        const int r1 = r0 + 8;
        #pragma unroll
        for (int nt = 0; nt < 3; ++nt) {
            const int col0 = 8 * nt + 2 * q;
            const int col1 = col0 + 1;
            C[m][nt][0] = (r0 == col0) ? 1.f : 0.f;
            C[m][nt][1] = (r0 == col1) ? 1.f : 0.f;
            C[m][nt][2] = (r1 == col0 && r1 < TT) ? 1.f : 0.f;
            C[m][nt][3] = (r1 == col1 && r1 < TT) ? 1.f : 0.f;
        }
    }

    float* Psm = reinterpret_cast<float*>(&As[0][0]) + wid * 2 * 672;
    int Mexp = 0;

    for (int i = 0; i < steps; ++i) {
        float* Ps = Psm + (i & 1) * 672;

        #pragma unroll
        for (int nt = 0; nt < 3; ++nt) {
            const int col = 8 * nt + 2 * q;
            *reinterpret_cast<float2*>(&Ps[g * 28 + col]) =
                make_float2(C[0][nt][0], C[0][nt][1]);
            *reinterpret_cast<float2*>(&Ps[(g + 8) * 28 + col]) =
                make_float2(C[0][nt][2], C[0][nt][3]);
            *reinterpret_cast<float2*>(&Ps[(16 + g) * 28 + col]) =
                make_float2(C[1][nt][0], C[1][nt][1]);
        }
        __syncwarp();

        unsigned Bf[3][3][2];
        #pragma unroll
        for (int ks = 0; ks < 3; ++ks)
            #pragma unroll
            for (int nt = 0; nt < 3; ++nt) {
                Bf[ks][nt][0] = f2tf32(Ps[(q + 8 * ks) * 28 + g + 8 * nt]);
                Bf[ks][nt][1] = f2tf32(Ps[(q + 4 + 8 * ks) * 28 + g + 8 * nt]);
            }

        // emissions for this step (bf16 -> f32 is a shift)
        const float x0 = __uint_as_float(
            (unsigned)xsm[wid][i * TT + g] << 16);
        const float x1 = __uint_as_float(
            (unsigned)xsm[wid][i * TT + g + 8] << 16);
        const float x2 = __uint_as_float(
            (unsigned)xsm[wid][i * TT + 16 + g] << 16);

        float Q[2][3][4];
        #pragma unroll
        for (int m = 0; m < 2; ++m)
            #pragma unroll
            for (int nt = 0; nt < 3; ++nt) {
                Q[m][nt][0] = 0.f; Q[m][nt][1] = 0.f;
                Q[m][nt][2] = 0.f; Q[m][nt][3] = 0.f;
                #pragma unroll
                for (int ks = 0; ks < 3; ++ks)
                    MMA_TF32(Q[m][nt][0], Q[m][nt][1], Q[m][nt][2], Q[m][nt][3],
                             A[m][ks][0], A[m][ks][1], A[m][ks][2], A[m][ks][3],
                             Bf[ks][nt][0], Bf[ks][nt][1]);
            }

        #pragma unroll
        for (int nt = 0; nt < 3; ++nt) {
            C[0][nt][0] = x0 * Q[0][nt][0];  C[0][nt][1] = x0 * Q[0][nt][1];
            C[0][nt][2] = x1 * Q[0][nt][2];  C[0][nt][3] = x1 * Q[0][nt][3];
            C[1][nt][0] = x2 * Q[1][nt][0];  C[1][nt][1] = x2 * Q[1][nt][1];
            C[1][nt][2] = 0.f;               C[1][nt][3] = 0.f;
        }

        if ((i & 3) == 3) {
            float mx = 0.f;
            #pragma unroll
            for (int m = 0; m < 2; ++m)
                #pragma unroll
                for (int nt = 0; nt < 3; ++nt) {
                    mx = fmaxf(mx, fmaxf(C[m][nt][0], C[m][nt][1]));
                    mx = fmaxf(mx, fmaxf(C[m][nt][2], C[m][nt][3]));
                }
            const unsigned mb =
                __reduce_max_sync(0xffffffffu, __float_as_uint(mx));
            const int e  = (int)(mb >> 23);
            const int en = (e == 0) ? 127 : e;
            const float nsc = __uint_as_float((unsigned)(254 - en) << 23);
            #pragma unroll
            for (int m = 0; m < 2; ++m)
                #pragma unroll
                for (int nt = 0; nt < 3; ++nt) {
                    C[m][nt][0] *= nsc; C[m][nt][1] *= nsc;
                    C[m][nt][2] *= nsc; C[m][nt][3] *= nsc;
                }
            Mexp += (en - 127);
        }
    }

    // store P_g and Mexp
    const int idx = b * SEG + gseg;
    float* Pg = g_P + (size_t)idx * 576;
    #pragma unroll
    for (int nt = 0; nt < 3; ++nt) {
        const int col = 8 * nt + 2 * q;
        *reinterpret_cast<float2*>(&Pg[g * TT + col]) =
            make_float2(C[0][nt][0], C[0][nt][1]);
        *reinterpret_cast<float2*>(&Pg[(g + 8) * TT + col]) =
            make_float2(C[0][nt][2], C[0][nt][3]);
        *reinterpret_cast<float2*>(&Pg[(16 + g) * TT + col]) =
            make_float2(C[1][nt][0], C[1][nt][1]);
    }
    if (lane == 0) g_M[idx] = Mexp;
}

// ---------------------------------------------------------------------------
// Combine: one 128-thread CTA per batch.  Stage all 16 P matrices into smem
// with coalesced float4 loads (parallel latency), then warp 0 folds from smem.
// ---------------------------------------------------------------------------
__global__ __launch_bounds__(128) void combine_kernel(
    const float* __restrict__ trans,
    float*       __restrict__ out)
{
    __shared__ float Pall[SEG * 576];            // 36.9 KB
    __shared__ __align__(16) float wbuf[2][32];

    const int tid = threadIdx.x;
    const int b = blockIdx.x;

    // stage P (coalesced)
    const float* gsrc = g_P + (size_t)b * SEG * 576;
    #pragma unroll 4
    for (int i = tid; i < SEG * 576 / 4; i += 128)
        *reinterpret_cast<float4*>(Pall + i * 4) =
            *reinterpret_cast<const float4*>(gsrc + i * 4);
    __syncthreads();

    if (tid >= 32) return;
    const int lane = tid;
    const int lanec = (lane < TT) ? lane : (TT - 1);

    const float u = (lane < TT) ? __expf(trans[TAG_STOP * TT + lane]) : 0.f;

    int mg = (lane < SEG) ? g_M[b * SEG + lane] : 0;
    #pragma unroll
    for (int o = 8; o > 0; o >>= 1)
        mg += __shfl_xor_sync(0xffffffffu, mg, o);
    int Mtot = mg;

    float v = (lane == TAG_START) ? 1.f : 0.f;

    #pragma unroll
    for (int g2 = 0; g2 < SEG; ++g2) {
        const int p = g2 & 1;
        wbuf[p][lane] = v;
        __syncwarp();

        const float* Pr = Pall + g2 * 576 + lanec * TT;
        const float4* vv = reinterpret_cast<const float4*>(&wbuf[p][0]);
        float a0 = 0.f, a1 = 0.f, a2 = 0.f, a3 = 0.f;
        #pragma unroll
        for (int i = 0; i < 6; ++i) {
            const float4 rr = *reinterpret_cast<const float4*>(Pr + i * 4);
            const float4 w4 = vv[i];
            a0 = fmaf(rr.x, w4.x, a0);
            a1 = fmaf(rr.y, w4.y, a1);
            a2 = fmaf(rr.z, w4.z, a2);
            a3 = fmaf(rr.w, w4.w, a3);
        }
        float vn = (a0 + a1) + (a2 + a3);
        vn = (lane < TT) ? vn : 0.f;

        const unsigned mb = __reduce_max_sync(0xffffffffu, __float_as_uint(vn));
        const int e  = (int)(mb >> 23);
        const int en = (e == 0) ? 127 : e;
        const float nsc = __uint_as_float((unsigned)(254 - en) << 23);
        v = vn * nsc;
        Mtot += (en - 127);
    }

    float term = v * u;
    #pragma unroll
    for (int o = 16; o > 0; o >>= 1)
        term += __shfl_xor_sync(0xffffffffu, term, o);

    if (lane == 0)
        out[b] = __logf(term) + (float)Mtot * 0.69314718055994531f;
}

extern "C" void kernel_launch(void* const* d_in, const int* in_sizes, int n_in,
                              void* d_out, int out_size)
{
    const float* feat   = (const float*)d_in[0];  // [128,512,512]
    const float* Wm     = (const float*)d_in[1];  // [24,512]
    const float* bias   = (const float*)d_in[2];  // [24]
    const float* trans  = (const float*)d_in[3];  // [24,24]
    const int*   lens   = (const int*)d_in[4];    // [128]
    float* out = (float*)d_out;                   // [128]

    fused_kernel<<<512, 128>>>(feat, Wm, bias, trans, lens);
    combine_kernel<<<128, 128>>>(trans, out);
}

// round 16
// speedup vs baseline: 1.0630x; 1.0307x over previous
#include <cuda_runtime.h>
#include <cmath>

#define BB 128
#define LL 512
#define HH 512
#define TT 24
#define TAG_START 22
#define TAG_STOP  23
#define SEG 16
#define SS  32            // steps per segment = LL/SEG
#define NQ  4             // quads per batch (4 segments each)

// Scratch (device globals; no allocations).
__device__ float g_P[BB * NQ * 576];         // quad transport matrices 1.2 MB
__device__ int   g_M[BB * NQ];               // quad exponent offsets

// m16n8k8 tf32 mma
#define MMA_TF32(c0,c1,c2,c3,a0,a1,a2,a3,b0,b1) \
  asm("mma.sync.aligned.m16n8k8.row.col.f32.tf32.tf32.f32 " \
      "{%0,%1,%2,%3},{%4,%5,%6,%7},{%8,%9},{%0,%1,%2,%3};" \
      : "+f"(c0),"+f"(c1),"+f"(c2),"+f"(c3) \
      : "r"(a0),"r"(a1),"r"(a2),"r"(a3),"r"(b0),"r"(b1))

// m16n8k16 bf16 mma
#define MMA_BF16(c0,c1,c2,c3,a0,a1,a2,a3,b0,b1) \
  asm("mma.sync.aligned.m16n8k16.row.col.f32.bf16.bf16.f32 " \
      "{%0,%1,%2,%3},{%4,%5,%6,%7},{%8,%9},{%0,%1,%2,%3};" \
      : "+f"(c0),"+f"(c1),"+f"(c2),"+f"(c3) \
      : "r"(a0),"r"(a1),"r"(a2),"r"(a3),"r"(b0),"r"(b1))

__device__ __forceinline__ unsigned f2tf32(float v) {
    unsigned r;
    asm("cvt.rna.tf32.f32 %0, %1;" : "=r"(r) : "f"(v));
    return r;
}

__device__ __forceinline__ unsigned pk_bf16x2(float lo, float hi) {
    unsigned r;
    asm("cvt.rn.bf16x2.f32 %0, %1, %2;" : "=r"(r) : "f"(hi), "f"(lo));
    return r;
}

#define CP_ASYNC16(dst, src) \
    asm volatile("cp.async.cg.shared.global [%0], [%1], 16;" \
                 :: "r"(dst), "l"(src))
#define CP_COMMIT()  asm volatile("cp.async.commit_group;")
#define CP_WAIT(n)   asm volatile("cp.async.wait_group %0;" :: "n"(n))

#define SK 520    // Wtn row stride in bf16 units
#define SAF 36    // A-stage row stride in fp32 units (32 used + 4 pad)
#define CCOL 32
#define NCH 16

// 24x24 matrix product Sd = Sa * Sb (all smem, row stride 28), tf32 mma.
// Warp-collective; returns the power-of-2 renorm exponent applied to Sd.
__device__ __forceinline__ int mat_product(
    const float* Sa, const float* Sb, float* Sd, int g, int q)
{
    unsigned Af[2][3][4];
    #pragma unroll
    for (int m = 0; m < 2; ++m) {
        const int r0 = 16 * m + g;
        const int r1 = r0 + 8;
        #pragma unroll
        for (int ks = 0; ks < 3; ++ks) {
            const int c0 = 8 * ks + q;
            const int c1 = c0 + 4;
            Af[m][ks][0] = f2tf32(Sa[r0 * 28 + c0]);
            Af[m][ks][1] = (r1 < TT) ? f2tf32(Sa[r1 * 28 + c0]) : 0u;
            Af[m][ks][2] = f2tf32(Sa[r0 * 28 + c1]);
            Af[m][ks][3] = (r1 < TT) ? f2tf32(Sa[r1 * 28 + c1]) : 0u;
        }
    }
    unsigned Bf[3][3][2];
    #pragma unroll
    for (int ks = 0; ks < 3; ++ks)
        #pragma unroll
        for (int nt = 0; nt < 3; ++nt) {
            Bf[ks][nt][0] = f2tf32(Sb[(q + 8 * ks) * 28 + g + 8 * nt]);
            Bf[ks][nt][1] = f2tf32(Sb[(q + 4 + 8 * ks) * 28 + g + 8 * nt]);
        }

    float Q[2][3][4];
    #pragma unroll
    for (int m = 0; m < 2; ++m)
        #pragma unroll
        for (int nt = 0; nt < 3; ++nt) {
            Q[m][nt][0] = 0.f; Q[m][nt][1] = 0.f;
            Q[m][nt][2] = 0.f; Q[m][nt][3] = 0.f;
            #pragma unroll
            for (int ks = 0; ks < 3; ++ks)
                MMA_TF32(Q[m][nt][0], Q[m][nt][1], Q[m][nt][2], Q[m][nt][3],
                         Af[m][ks][0], Af[m][ks][1], Af[m][ks][2], Af[m][ks][3],
                         Bf[ks][nt][0], Bf[ks][nt][1]);
        }

    // renorm (exact power-of-2)
    float mx = 0.f;
    #pragma unroll
    for (int m = 0; m < 2; ++m)
        #pragma unroll
        for (int nt = 0; nt < 3; ++nt) {
            mx = fmaxf(mx, fmaxf(Q[m][nt][0], Q[m][nt][1]));
            mx = fmaxf(mx, fmaxf(Q[m][nt][2], Q[m][nt][3]));
        }
    const unsigned mb = __reduce_max_sync(0xffffffffu, __float_as_uint(mx));
    const int e  = (int)(mb >> 23);
    const int en = (e == 0) ? 127 : e;
    const float nsc = __uint_as_float((unsigned)(254 - en) << 23);

    #pragma unroll
    for (int nt = 0; nt < 3; ++nt) {
        const int col = 8 * nt + 2 * q;
        *reinterpret_cast<float2*>(const_cast<float*>(&Sd[g * 28 + col])) =
            make_float2(Q[0][nt][0] * nsc, Q[0][nt][1] * nsc);
        *reinterpret_cast<float2*>(const_cast<float*>(&Sd[(g + 8) * 28 + col])) =
            make_float2(Q[0][nt][2] * nsc, Q[0][nt][3] * nsc);
        *reinterpret_cast<float2*>(const_cast<float*>(&Sd[(16 + g) * 28 + col])) =
            make_float2(Q[1][nt][0] * nsc, Q[1][nt][1] * nsc);
    }
    __syncwarp();
    return en - 127;
}

// ---------------------------------------------------------------------------
// Fused kernel (R13 config): emission GEMM (bf16 mma, cp.async ring) +
// per-segment transport chain (tf32 mma) + in-CTA quad-fold of the 4 segment
// matrices into ONE matrix (2-level mma tree) -> 4x less combine traffic.
// ---------------------------------------------------------------------------
__global__ void __launch_bounds__(128, 2) fused_kernel(
    const float* __restrict__ feat,
    const float* __restrict__ Wm,
    const float* __restrict__ bias,
    const float* __restrict__ trans,
    const int*   __restrict__ lengths)
{
    __shared__ unsigned short Wtn[TT * SK];   // 24.4 KB bf16 W^T [n][k]
    __shared__ float As[4][128 * SAF];        // 73.7 KB A ring / Psm / fold
    __shared__ float xsm[4][SS * TT];         // 12.3 KB emissions per warp
    __shared__ int quadM[4];

    const int tid = threadIdx.x;
    const int b    = blockIdx.x >> 2;
    const int quad = blockIdx.x & 3;
    const long rowCTA = (long)b * LL + quad * 128;

    const int row16 = tid >> 3;
    const int col4  = tid & 7;

    // ---- phase 1 prologue
    #pragma unroll
    for (int c = 0; c < 3; ++c) {
        #pragma unroll
        for (int i = 0; i < 8; ++i) {
            const int row = row16 + 16 * i;
            const float* src = feat + (rowCTA + row) * HH + c * CCOL + col4 * 4;
            const unsigned dst = (unsigned)__cvta_generic_to_shared(
                &As[c][row * SAF + col4 * 4]);
            CP_ASYNC16(dst, src);
        }
        CP_COMMIT();
    }

    for (int idx = tid; idx < TT * (HH / 4); idx += 128) {
        const int n  = idx >> 7;
        const int kq = idx & 127;
        const float4 wv = *reinterpret_cast<const float4*>(Wm + n * HH + kq * 4);
        uint2 p;
        p.x = pk_bf16x2(wv.x, wv.y);
        p.y = pk_bf16x2(wv.z, wv.w);
        *reinterpret_cast<uint2*>(&Wtn[n * SK + kq * 4]) = p;
    }

    const int lane = tid & 31;
    const int wid  = tid >> 5;
    const int g = lane >> 2;
    const int q = lane & 3;

    float C[2][3][4];
    #pragma unroll
    for (int mm = 0; mm < 2; ++mm)
        #pragma unroll
        for (int nt = 0; nt < 3; ++nt)
            { C[mm][nt][0]=0.f; C[mm][nt][1]=0.f; C[mm][nt][2]=0.f; C[mm][nt][3]=0.f; }

    // ---- phase 1 main loop
    #pragma unroll
    for (int c = 0; c < NCH; ++c) {
        CP_WAIT(2);
        __syncthreads();

        if (c + 3 < NCH) {
            const int cn = c + 3;
            #pragma unroll
            for (int i = 0; i < 8; ++i) {
                const int row = row16 + 16 * i;
                const float* src =
                    feat + (rowCTA + row) * HH + cn * CCOL + col4 * 4;
                const unsigned dst = (unsigned)__cvta_generic_to_shared(
                    &As[cn & 3][row * SAF + col4 * 4]);
                CP_ASYNC16(dst, src);
            }
        }
        CP_COMMIT();

        const float* Ac = &As[c & 3][0];
        #pragma unroll
        for (int kk = 0; kk < 2; ++kk) {
            const int kl = kk * 16;
            const int kg = c * CCOL + kl;
            #pragma unroll
            for (int mm = 0; mm < 2; ++mm) {
                const int r = wid * 32 + mm * 16 + g;
                const float2 f0 = *reinterpret_cast<const float2*>(
                    &Ac[r * SAF + kl + 2 * q]);
                const float2 f1 = *reinterpret_cast<const float2*>(
                    &Ac[(r + 8) * SAF + kl + 2 * q]);
                const float2 f2 = *reinterpret_cast<const float2*>(
                    &Ac[r * SAF + kl + 8 + 2 * q]);
                const float2 f3 = *reinterpret_cast<const float2*>(
                    &Ac[(r + 8) * SAF + kl + 8 + 2 * q]);
                const unsigned a0 = pk_bf16x2(f0.x, f0.y);
                const unsigned a1 = pk_bf16x2(f1.x, f1.y);
                const unsigned a2 = pk_bf16x2(f2.x, f2.y);
                const unsigned a3 = pk_bf16x2(f3.x, f3.y);
                #pragma unroll
                for (int nt = 0; nt < 3; ++nt) {
                    const int n = 8 * nt + g;
                    const unsigned b0 = *reinterpret_cast<const unsigned*>(
                        &Wtn[n * SK + kg + 2 * q]);
                    const unsigned b1 = *reinterpret_cast<const unsigned*>(
                        &Wtn[n * SK + kg + 8 + 2 * q]);
                    MMA_BF16(C[mm][nt][0], C[mm][nt][1], C[mm][nt][2], C[mm][nt][3],
                             a0, a1, a2, a3, b0, b1);
                }
            }
        }
    }
    CP_WAIT(0);

    // ---- epilogue: bias + exp -> xsm
    #pragma unroll
    for (int mm = 0; mm < 2; ++mm) {
        const int i0 = mm * 16 + g;
        #pragma unroll
        for (int nt = 0; nt < 3; ++nt) {
            const int col = nt * 8 + 2 * q;
            const float bv0 = __ldg(bias + col);
            const float bv1 = __ldg(bias + col + 1);
            *reinterpret_cast<float2*>(&xsm[wid][i0 * TT + col]) =
                make_float2(__expf(C[mm][nt][0] + bv0),
                            __expf(C[mm][nt][1] + bv1));
            *reinterpret_cast<float2*>(&xsm[wid][(i0 + 8) * TT + col]) =
                make_float2(__expf(C[mm][nt][2] + bv0),
                            __expf(C[mm][nt][3] + bv1));
        }
    }
    __syncthreads();

    // ================= phase 2: segment transport chain =================
    const int gseg = quad * 4 + wid;
    const int len = lengths[b];
    int steps = len - gseg * SS;
    steps = (steps < 0) ? 0 : ((steps > SS) ? SS : steps);

    unsigned A[2][3][4];
    #pragma unroll
    for (int m = 0; m < 2; ++m) {
        const int r0 = 16 * m + g;
        const int r1 = r0 + 8;
        #pragma unroll
        for (int ks = 0; ks < 3; ++ks) {
            const int c0 = 8 * ks + q;
            const int c1 = c0 + 4;
            A[m][ks][0] = (r0 < TT) ? f2tf32(__expf(trans[r0 * TT + c0])) : 0u;
            A[m][ks][1] = (r1 < TT) ? f2tf32(__expf(trans[r1 * TT + c0])) : 0u;
            A[m][ks][2] = (r0 < TT) ? f2tf32(__expf(trans[r0 * TT + c1])) : 0u;
            A[m][ks][3] = (r1 < TT) ? f2tf32(__expf(trans[r1 * TT + c1])) : 0u;
        }
    }

    #pragma unroll
    for (int m = 0; m < 2; ++m) {
        const int r0 = 16 * m + g;
        const int r1 = r0 + 8;
        #pragma unroll
        for (int nt = 0; nt < 3; ++nt) {
            const int col0 = 8 * nt + 2 * q;
            const int col1 = col0 + 1;
            C[m][nt][0] = (r0 == col0) ? 1.f : 0.f;
            C[m][nt][1] = (r0 == col1) ? 1.f : 0.f;
            C[m][nt][2] = (r1 == col0 && r1 < TT) ? 1.f : 0.f;
            C[m][nt][3] = (r1 == col1 && r1 < TT) ? 1.f : 0.f;
        }
    }

    float* Psm = reinterpret_cast<float*>(&As[0][0]) + wid * 2 * 672;
    int Mexp = 0;

    for (int i = 0; i < steps; ++i) {
        float* Ps = Psm + (i & 1) * 672;

        #pragma unroll
        for (int nt = 0; nt < 3; ++nt) {
            const int col = 8 * nt + 2 * q;
            *reinterpret_cast<float2*>(&Ps[g * 28 + col]) =
                make_float2(C[0][nt][0], C[0][nt][1]);
            *reinterpret_cast<float2*>(&Ps[(g + 8) * 28 + col]) =
                make_float2(C[0][nt][2], C[0][nt][3]);
            *reinterpret_cast<float2*>(&Ps[(16 + g) * 28 + col]) =
                make_float2(C[1][nt][0], C[1][nt][1]);
        }
        __syncwarp();

        unsigned Bf[3][3][2];
        #pragma unroll
        for (int ks = 0; ks < 3; ++ks)
            #pragma unroll
            for (int nt = 0; nt < 3; ++nt) {
                Bf[ks][nt][0] = f2tf32(Ps[(q + 8 * ks) * 28 + g + 8 * nt]);
                Bf[ks][nt][1] = f2tf32(Ps[(q + 4 + 8 * ks) * 28 + g + 8 * nt]);
            }

        const float x0 = xsm[wid][i * TT + g];
        const float x1 = xsm[wid][i * TT + g + 8];
        const float x2 = xsm[wid][i * TT + 16 + g];

        float Q[2][3][4];
        #pragma unroll
        for (int m = 0; m < 2; ++m)
            #pragma unroll
            for (int nt = 0; nt < 3; ++nt) {
                Q[m][nt][0] = 0.f; Q[m][nt][1] = 0.f;
                Q[m][nt][2] = 0.f; Q[m][nt][3] = 0.f;
                #pragma unroll
                for (int ks = 0; ks < 3; ++ks)
                    MMA_TF32(Q[m][nt][0], Q[m][nt][1], Q[m][nt][2], Q[m][nt][3],
                             A[m][ks][0], A[m][ks][1], A[m][ks][2], A[m][ks][3],
                             Bf[ks][nt][0], Bf[ks][nt][1]);
            }

        #pragma unroll
        for (int nt = 0; nt < 3; ++nt) {
            C[0][nt][0] = x0 * Q[0][nt][0];  C[0][nt][1] = x0 * Q[0][nt][1];
            C[0][nt][2] = x1 * Q[0][nt][2];  C[0][nt][3] = x1 * Q[0][nt][3];
            C[1][nt][0] = x2 * Q[1][nt][0];  C[1][nt][1] = x2 * Q[1][nt][1];
            C[1][nt][2] = 0.f;               C[1][nt][3] = 0.f;
        }

        if ((i & 3) == 3) {
            float mx = 0.f;
            #pragma unroll
            for (int m = 0; m < 2; ++m)
                #pragma unroll
                for (int nt = 0; nt < 3; ++nt) {
                    mx = fmaxf(mx, fmaxf(C[m][nt][0], C[m][nt][1]));
                    mx = fmaxf(mx, fmaxf(C[m][nt][2], C[m][nt][3]));
                }
            const unsigned mb =
                __reduce_max_sync(0xffffffffu, __float_as_uint(mx));
            const int e  = (int)(mb >> 23);
            const int en = (e == 0) ? 127 : e;
            const float nsc = __uint_as_float((unsigned)(254 - en) << 23);
            #pragma unroll
            for (int m = 0; m < 2; ++m)
                #pragma unroll
                for (int nt = 0; nt < 3; ++nt) {
                    C[m][nt][0] *= nsc; C[m][nt][1] *= nsc;
                    C[m][nt][2] *= nsc; C[m][nt][3] *= nsc;
                }
            Mexp += (en - 127);
        }
    }

    // ================= quad-fold: P_quad = P3*P2*P1*P0 ==================
    __syncthreads();   // all warps done with their Psm double buffers

    float* Fold = reinterpret_cast<float*>(&As[0][0]);
    // store my segment matrix to Fold + wid*672 (stride 28)
    {
        float* Ps = Fold + wid * 672;
        #pragma unroll
        for (int nt = 0; nt < 3; ++nt) {
            const int col = 8 * nt + 2 * q;
            *reinterpret_cast<float2*>(&Ps[g * 28 + col]) =
                make_float2(C[0][nt][0], C[0][nt][1]);
            *reinterpret_cast<float2*>(&Ps[(g + 8) * 28 + col]) =
                make_float2(C[0][nt][2], C[0][nt][3]);
            *reinterpret_cast<float2*>(&Ps[(16 + g) * 28 + col]) =
                make_float2(C[1][nt][0], C[1][nt][1]);
        }
        if (lane == 0) quadM[wid] = Mexp;
    }
    __syncthreads();

    // level 1: M01 = P1*P0 (warp 0), M23 = P3*P2 (warp 1)
    if (wid == 0) {
        const int e01 = mat_product(Fold + 672, Fold, Fold + 4 * 672, g, q);
        if (lane == 0) quadM[0] += e01;
    } else if (wid == 1) {
        const int e23 = mat_product(Fold + 3 * 672, Fold + 2 * 672,
                                    Fold + 5 * 672, g, q);
        if (lane == 0) quadM[1] += e23;
    }
    __syncthreads();

    // level 2: P_quad = M23 * M01 -> Fold[0]
    if (wid == 0) {
        const int ef = mat_product(Fold + 5 * 672, Fold + 4 * 672, Fold, g, q);
        if (lane == 0) quadM[0] += ef;
    }
    __syncthreads();

    // store P_quad (dense 24x24) and Mexp
    float* Pg = g_P + (size_t)(b * NQ + quad) * 576;
    for (int i = tid; i < 576; i += 128) {
        const int r = i / TT;
        const int c = i - r * TT;
        Pg[i] = Fold[r * 28 + c];
    }
    if (tid == 0)
        g_M[b * NQ + quad] = quadM[0] + quadM[1] + quadM[2] + quadM[3];
}

// ---------------------------------------------------------------------------
// Combine: one 128-thread CTA per batch; stage 4 quad matrices (9.2 KB) into
// smem coalesced, then warp 0 folds 4 steps.
// ---------------------------------------------------------------------------
__global__ __launch_bounds__(128) void combine_kernel(
    const float* __restrict__ trans,
    float*       __restrict__ out)
{
    __shared__ float Pall[NQ * 576];             // 9.2 KB
    __shared__ __align__(16) float wbuf[2][32];

    const int tid = threadIdx.x;
    const int b = blockIdx.x;

    const float* gsrc = g_P + (size_t)b * NQ * 576;
    #pragma unroll
    for (int i = tid; i < NQ * 576 / 4; i += 128)
        *reinterpret_cast<float4*>(Pall + i * 4) =
            *reinterpret_cast<const float4*>(gsrc + i * 4);
    __syncthreads();

    if (tid >= 32) return;
    const int lane = tid;
    const int lanec = (lane < TT) ? lane : (TT - 1);

    const float u = (lane < TT) ? __expf(trans[TAG_STOP * TT + lane]) : 0.f;

    int mg = (lane < NQ) ? g_M[b * NQ + lane] : 0;
    #pragma unroll
    for (int o = 2; o > 0; o >>= 1)
        mg += __shfl_xor_sync(0xffffffffu, mg, o);
    int Mtot = __shfl_sync(0xffffffffu, mg, 0);

    float v = (lane == TAG_START) ? 1.f : 0.f;

    #pragma unroll
    for (int g2 = 0; g2 < NQ; ++g2) {
        const int p = g2 & 1;
        wbuf[p][lane] = v;
        __syncwarp();

        const float* Pr = Pall + g2 * 576 + lanec * TT;
        const float4* vv = reinterpret_cast<const float4*>(&wbuf[p][0]);
        float a0 = 0.f, a1 = 0.f, a2 = 0.f, a3 = 0.f;
        #pragma unroll
        for (int i = 0; i < 6; ++i) {
            const float4 rr = *reinterpret_cast<const float4*>(Pr + i * 4);
            const float4 w4 = vv[i];
            a0 = fmaf(rr.x, w4.x, a0);
            a1 = fmaf(rr.y, w4.y, a1);
            a2 = fmaf(rr.z, w4.z, a2);
            a3 = fmaf(rr.w, w4.w, a3);
        }
        float vn = (a0 + a1) + (a2 + a3);
        vn = (lane < TT) ? vn : 0.f;

        const unsigned mb = __reduce_max_sync(0xffffffffu, __float_as_uint(vn));
        const int e  = (int)(mb >> 23);
        const int en = (e == 0) ? 127 : e;
        const float nsc = __uint_as_float((unsigned)(254 - en) << 23);
        v = vn * nsc;
        Mtot += (en - 127);
    }

    float term = v * u;
    #pragma unroll
    for (int o = 16; o > 0; o >>= 1)
        term += __shfl_xor_sync(0xffffffffu, term, o);

    if (lane == 0)
        out[b] = __logf(term) + (float)Mtot * 0.69314718055994531f;
}

extern "C" void kernel_launch(void* const* d_in, const int* in_sizes, int n_in,
                              void* d_out, int out_size)
{
    const float* feat   = (const float*)d_in[0];  // [128,512,512]
    const float* Wm     = (const float*)d_in[1];  // [24,512]
    const float* bias   = (const float*)d_in[2];  // [24]
    const float* trans  = (const float*)d_in[3];  // [24,24]
    const int*   lens   = (const int*)d_in[4];    // [128]
    float* out = (float*)d_out;                   // [128]

    fused_kernel<<<512, 128>>>(feat, Wm, bias, trans, lens);
    combine_kernel<<<128, 128>>>(trans, out);
}